// round 9
// baseline (speedup 1.0000x reference)
#include <cuda_runtime.h>

#define NROWS   32768
#define DCOLS   2048
#define C4TOT   (DCOLS / 4)          // 512 float4 columns per row
#define SLABC4  128                  // float4 cols per slab = 512 scalar cols = 64 MB
#define NSLABS  (C4TOT / SLABC4)     // 4
#define EPS     1e-6f

// Allocation-free scratch (__device__ globals). Returned to zero by the
// kernels themselves, so graph replays see identical initial state.
__device__ float g_u[DCOLS];         // column sum-of-squares accumulators
__device__ float g_s[DCOLS];         // rsqrt scales
__device__ int   g_cnt[DCOLS];       // per-column arrival counters

// ---------------------------------------------------------------------------
// Phase A: reduce one 64MB slab. Grid = G blocks x 512 threads. Measured at
// ~6.4 TB/s (roofline) in rounds 5/8 — unchanged.
__global__ void __launch_bounds__(512)
reduceA_kernel(const float4* __restrict__ x, int slab, int G) {
    const int tid = threadIdx.x;
    const int c4l = tid & (SLABC4 - 1);             // 0..127
    const int w   = (blockIdx.x << 2) + (tid >> 7); // row worker id
    const int W   = G << 2;                         // total row workers
    const size_t coff = (size_t)slab * SLABC4 + c4l;

    float ax = 0.f, ay = 0.f, az = 0.f, aw = 0.f;
    int r = w;
    for (; r + 3 * W < NROWS; r += 4 * W) {
        float4 v0 = x[(size_t)(r        ) * C4TOT + coff];
        float4 v1 = x[(size_t)(r +     W) * C4TOT + coff];
        float4 v2 = x[(size_t)(r + 2 * W) * C4TOT + coff];
        float4 v3 = x[(size_t)(r + 3 * W) * C4TOT + coff];
        ax = fmaf(v0.x, v0.x, ax); ay = fmaf(v0.y, v0.y, ay);
        az = fmaf(v0.z, v0.z, az); aw = fmaf(v0.w, v0.w, aw);
        ax = fmaf(v1.x, v1.x, ax); ay = fmaf(v1.y, v1.y, ay);
        az = fmaf(v1.z, v1.z, az); aw = fmaf(v1.w, v1.w, aw);
        ax = fmaf(v2.x, v2.x, ax); ay = fmaf(v2.y, v2.y, ay);
        az = fmaf(v2.z, v2.z, az); aw = fmaf(v2.w, v2.w, aw);
        ax = fmaf(v3.x, v3.x, ax); ay = fmaf(v3.y, v3.y, ay);
        az = fmaf(v3.z, v3.z, az); aw = fmaf(v3.w, v3.w, aw);
    }
    for (; r < NROWS; r += W) {
        float4 v = x[(size_t)r * C4TOT + coff];
        ax = fmaf(v.x, v.x, ax); ay = fmaf(v.y, v.y, ay);
        az = fmaf(v.z, v.z, az); aw = fmaf(v.w, v.w, aw);
    }

    __shared__ float sacc[4][SLABC4 * 4];
    const int rw = tid >> 7;
    sacc[rw][c4l * 4 + 0] = ax;
    sacc[rw][c4l * 4 + 1] = ay;
    sacc[rw][c4l * 4 + 2] = az;
    sacc[rw][c4l * 4 + 3] = aw;
    __syncthreads();

    const int scol = slab * (SLABC4 * 4) + tid;     // global scalar column
    float v = sacc[0][tid] + sacc[1][tid] + sacc[2][tid] + sacc[3][tid];
    atomicAdd(&g_u[scol], v);
    __threadfence();                                 // publish before counting
    if (atomicAdd(&g_cnt[scol], 1) == G - 1) {       // everyone has published
        float total = atomicExch(&g_u[scol], 0.0f);  // complete sum + reset
        g_s[scol]   = rsqrtf(total + EPS);
        g_cnt[scol] = 0;                             // reset for next replay
    }
}

// ---------------------------------------------------------------------------
// Phase B: stream one slab as ONE even wave. Grid = 8*nsm blocks x 256 thr
// (2048 threads/SM, all blocks co-resident -> zero wave raggedness). Each
// grid-stride iteration handles one quarter-space index = 4 row-strided
// float4 positions: 4 independent ldcs batched before 4 stcs (MLP=4, stores
// never block the loads of the same batch).
#define QSPACE ((NROWS / 4) * SLABC4)                 // 1,048,576 per slab

__global__ void __launch_bounds__(256)
scaleB_kernel(const float4* __restrict__ x, float4* __restrict__ y, int slab) {
    const unsigned stride = gridDim.x * 256u;
    const size_t   step   = (size_t)(NROWS / 4) * C4TOT;   // 8192-row stride
    const size_t   soff   = (size_t)slab * SLABC4;

    for (unsigned j = blockIdx.x * 256u + threadIdx.x; j < QSPACE; j += stride) {
        const int      c4l = j & (SLABC4 - 1);             // 0..127
        const unsigned rq  = j >> 7;                       // row within quarter
        const size_t base  = (size_t)rq * C4TOT + soff + c4l;

        const float4 s = ((const float4*)g_s)[slab * SLABC4 + c4l];

        float4 v0 = __ldcs(x + base);
        float4 v1 = __ldcs(x + base +     step);
        float4 v2 = __ldcs(x + base + 2 * step);
        float4 v3 = __ldcs(x + base + 3 * step);
        v0.x *= s.x; v0.y *= s.y; v0.z *= s.z; v0.w *= s.w;
        v1.x *= s.x; v1.y *= s.y; v1.z *= s.z; v1.w *= s.w;
        v2.x *= s.x; v2.y *= s.y; v2.z *= s.z; v2.w *= s.w;
        v3.x *= s.x; v3.y *= s.y; v3.z *= s.z; v3.w *= s.w;
        __stcs(y + base,            v0);
        __stcs(y + base +     step, v1);
        __stcs(y + base + 2 * step, v2);
        __stcs(y + base + 3 * step, v3);
    }
}

// ---------------------------------------------------------------------------
extern "C" void kernel_launch(void* const* d_in, const int* in_sizes, int n_in,
                              void* d_out, int out_size) {
    const float4* x = (const float4*)d_in[0];
    float4*       y = (float4*)d_out;

    static int nsm = 0;
    if (nsm == 0) {
        cudaDeviceProp prop;
        cudaGetDeviceProperties(&prop, 0);
        nsm = prop.multiProcessorCount;               // 152 on GB300
    }
    const int G  = 2 * nsm;                           // A: even waves
    const int GB = 8 * nsm;                           // B: exactly one full wave

    for (int slab = 0; slab < NSLABS; ++slab) {
        reduceA_kernel<<<G, 512>>>(x, slab, G);
        scaleB_kernel<<<GB, 256>>>(x, y, slab);
    }
}